// round 15
// baseline (speedup 1.0000x reference)
#include <cuda_runtime.h>
#include <cuda_fp16.h>
#include <cstdint>

#define BB 4
#define HH 16
#define SS_ 2048
#define DD 64
#define BQ 128
#define BK 64
#define NKT 32
#define NBH 64
#define NT 256
#define VSTRU 72               /* V fp16x2 smem row stride in u32 */
#define KSTRU 40               /* K bf16x2 smem row stride in u32 (LDS.64) */
#define KBUFU (64*KSTRU)       /* 2560 u32 = 10240 B */
#define VBUFU (32*VSTRU)       /* 2304 u32 =  9216 B */
#define STAGEU (KBUFU+VBUFU)   /* 4864 u32 = 19456 B */
#define LOG2E 1.4426950408889634f
#define LN2   0.6931471805599453f

__device__ float    g_vpart[NBH*8*64];
__device__ uint32_t g_kbf[(size_t)NBH*SS_*(DD/2)];   /* bf16x2, permuted d-pair cols */
__device__ uint32_t g_vh [(size_t)NBH*(SS_/2)*DD];   /* fp16x2 pairs along k */
__device__ uint4    g_mfrag[524288];

// ---------------- helpers ----------------
__device__ __forceinline__ uint32_t smem_u32(const void* p) {
    uint32_t a;
    asm("{ .reg .u64 t; cvta.to.shared.u64 t, %1; cvt.u32.u64 %0, t; }"
        : "=r"(a) : "l"(p));
    return a;
}
__device__ __forceinline__ uint32_t bf2(float lo, float hi) {
    uint32_t r; asm("cvt.rn.bf16x2.f32 %0, %1, %2;" : "=r"(r) : "f"(hi), "f"(lo));
    return r;
}
__device__ __forceinline__ uint32_t h2(float lo, float hi) {
    uint32_t r; asm("cvt.rn.f16x2.f32 %0, %1, %2;" : "=r"(r) : "f"(hi), "f"(lo));
    return r;
}
__device__ __forceinline__ uint32_t ex2h2(uint32_t a) {
    uint32_t d; asm("ex2.approx.f16x2 %0, %1;" : "=r"(d) : "r"(a)); return d;
}
__device__ __forceinline__ uint32_t hadd2u(uint32_t a, uint32_t b) {
    uint32_t d; asm("add.rn.f16x2 %0, %1, %2;" : "=r"(d) : "r"(a), "r"(b)); return d;
}
__device__ __forceinline__ void mma16bf(float* d, const uint32_t* a,
                                        uint32_t b0, uint32_t b1) {
    asm volatile(
        "mma.sync.aligned.m16n8k16.row.col.f32.bf16.bf16.f32 "
        "{%0,%1,%2,%3}, {%4,%5,%6,%7}, {%8,%9}, {%0,%1,%2,%3};"
        : "+f"(d[0]), "+f"(d[1]), "+f"(d[2]), "+f"(d[3])
        : "r"(a[0]), "r"(a[1]), "r"(a[2]), "r"(a[3]), "r"(b0), "r"(b1));
}
__device__ __forceinline__ void mma16f(float* d, const uint32_t* a,
                                       uint32_t b0, uint32_t b1) {
    asm volatile(
        "mma.sync.aligned.m16n8k16.row.col.f32.f16.f16.f32 "
        "{%0,%1,%2,%3}, {%4,%5,%6,%7}, {%8,%9}, {%0,%1,%2,%3};"
        : "+f"(d[0]), "+f"(d[1]), "+f"(d[2]), "+f"(d[3])
        : "r"(a[0]), "r"(a[1]), "r"(a[2]), "r"(a[3]), "r"(b0), "r"(b1));
}
__device__ __forceinline__ void cpa16(uint32_t sdst, const void* gsrc) {
    asm volatile("cp.async.cg.shared.global [%0], [%1], 16;"
                 :: "r"(sdst), "l"(gsrc));
}
#define CP_COMMIT()  asm volatile("cp.async.commit_group;" ::: "memory")
#define CP_WAIT0()   asm volatile("cp.async.wait_group 0;" ::: "memory")
#define HBAR(id)     asm volatile("bar.sync %0, 128;" :: "r"(id) : "memory")

// ---------------------------------------------------------------------------
// prep: mask-fragments + K->bf16x2(permuted) + V->fp16x2(plain) + vsum512
// ---------------------------------------------------------------------------
__global__ void prep_kernel(const float* __restrict__ gk,
                            const float* __restrict__ gv,
                            const int*   __restrict__ gm)
{
    __shared__ float red[4][64];
    const int bid = blockIdx.x, tid = threadIdx.x;

    if (bid < 2048) {                       // mask AND-fragments
        int i  = bid*256 + tid;
        int t  = i & 3;
        int g  = (i >> 2) & 7;
        int c4 = (i >> 5) & 3;
        int kt = (i >> 7) & 31;
        int pp = i >> 12;
        int qlo = pp*16 + g, qhi = qlo + 8;
        int kE  = kt*64 + 16*c4 + 2*t, kO = kE + 8;
        const int* ml = gm + (size_t)qlo*SS_;
        const int* mh = gm + (size_t)qhi*SS_;
        uint4 o;
        o.x = (ml[kE] ? 0xFFFFu : 0u) | (ml[kE+1] ? 0xFFFF0000u : 0u);
        o.y = (mh[kE] ? 0xFFFFu : 0u) | (mh[kE+1] ? 0xFFFF0000u : 0u);
        o.z = (ml[kO] ? 0xFFFFu : 0u) | (ml[kO+1] ? 0xFFFF0000u : 0u);
        o.w = (mh[kO] ? 0xFFFFu : 0u) | (mh[kO+1] ? 0xFFFF0000u : 0u);
        g_mfrag[i] = o;
    } else if (bid < 6144) {                // K -> bf16x2, permuted d-pair cols
        size_t i = (size_t)(bid - 2048)*256 + tid;
        const float4* src = (const float4*)gk + i*2;
        float4 a = src[0], b = src[1];
        size_t row = i >> 3;
        int    aa  = (int)(i & 7);
        uint32_t* dst = g_kbf + row*64 + 8*(aa >> 1) + (aa & 1);
        dst[0] = bf2(a.x, a.y);
        dst[2] = bf2(a.z, a.w);
        dst[4] = bf2(b.x, b.y);
        dst[6] = bf2(b.z, b.w);
    } else if (bid < 10240) {               // V -> fp16x2 (pairs along k, plain)
        size_t i = (size_t)(bid - 6144)*256 + tid;
        size_t R = i >> 4;
        int    q = (int)(i & 15);
        const float4* v4 = (const float4*)gv;
        float4 f0 = v4[(2*R    )*16 + q];
        float4 f1 = v4[(2*R + 1)*16 + q];
        uint4 o;
        o.x = h2(f0.x, f1.x); o.y = h2(f0.y, f1.y);
        o.z = h2(f0.z, f1.z); o.w = h2(f0.w, f1.w);
        ((uint4*)g_vh)[i] = o;
    } else {                                // vsum partials: 512 blocks
        int blk  = bid - 10240;
        int bh   = blk >> 3, part = blk & 7;
        int d = tid & 63, strip = tid >> 6;
        const float* vp = gv + (size_t)bh*SS_*DD + (size_t)part*256*DD;
        float a0 = 0.f, a1 = 0.f, a2 = 0.f, a3 = 0.f;
        #pragma unroll 4
        for (int k = strip; k < 256; k += 16) {
            a0 += vp[(k     )*DD + d];
            a1 += vp[(k +  4)*DD + d];
            a2 += vp[(k +  8)*DD + d];
            a3 += vp[(k + 12)*DD + d];
        }
        red[strip][d] = (a0 + a1) + (a2 + a3);
        __syncthreads();
        if (strip == 0)
            g_vpart[blk*64 + d] = red[0][d] + red[1][d] + red[2][d] + red[3][d];
    }
}

// ---------------------------------------------------------------------------
// main attention kernel — split-CTA dual pipelines (2 x 4-warp halves)
//   out = (ln2*A1 - lse*A2) - 1e9*(A3 - A2);  S-mma emits s*log2e
// ---------------------------------------------------------------------------
__global__ void __launch_bounds__(NT, 2)
attn_kernel(const float* __restrict__ gq, float* __restrict__ gout)
{
    extern __shared__ uint32_t smu[];
    __shared__ float vs_s[64];

    const uint32_t smbase = smem_u32(smu);

    const int tid  = threadIdx.x;
    const int w    = tid >> 5;
    const int lane = tid & 31;
    const int g = lane >> 2;
    const int t = lane & 3;
    const int hb   = tid >> 7;        // half index 0/1 (warps 0-3 / 4-7)
    const int htid = tid & 127;       // thread id within half
    const int bid = blockIdx.x;
    const int bh  = bid >> 4;
    const int qt  = bid & 15;
    const int qbase = qt * BQ;
    const int qlo = qbase + 16*w + g;
    const int qhi = qlo + 8;

    if (tid < 64) {
        const float* vpp = g_vpart + (size_t)bh*8*64 + tid;
        float s = 0.f;
        #pragma unroll
        for (int p = 0; p < 8; p++) s += vpp[p*64];
        vs_s[tid] = s;
    }

    // ---- persistent Q fragments: bf16 pairs, pre-scaled by log2e/8 ----
    uint32_t Qf[4][4];
    {
        const float qs = 0.125f * LOG2E;
        const float* ql = gq + (size_t)bh*SS_*DD + (size_t)qlo*DD;
        const float* qh = gq + (size_t)bh*SS_*DD + (size_t)qhi*DD;
        #pragma unroll
        for (int c4 = 0; c4 < 4; c4++) {
            int k0 = 16*c4 + 2*t;
            Qf[c4][0] = bf2(qs*ql[k0    ], qs*ql[k0 + 1]);
            Qf[c4][1] = bf2(qs*qh[k0    ], qs*qh[k0 + 1]);
            Qf[c4][2] = bf2(qs*ql[k0 + 8], qs*ql[k0 + 9]);
            Qf[c4][3] = bf2(qs*qh[k0 + 8], qs*qh[k0 + 9]);
        }
    }

    const char* kgb = (const char*)g_kbf + (size_t)bh*SS_*128;
    const char* vgb = (const char*)g_vh  + (size_t)bh*(SS_/2)*256;
    const uint4* mfb = g_mfrag + (((size_t)(qt*8 + w)*32)*4)*32 + lane;

    float A1[8][4], A2[8][4];
    #pragma unroll
    for (int nb = 0; nb < 8; nb++)
        #pragma unroll
        for (int j = 0; j < 4; j++) { A1[nb][j] = 0.f; A2[nb][j] = 0.f; }
    uint32_t lsum2_lo = 0u, lsum2_hi = 0u;

    // per-half pipeline: stage base (u32 units) and byte addr
    const uint32_t hbase_u = (uint32_t)hb * 2u * STAGEU;
    const uint32_t hbase_a = smbase + hbase_u*4u;

    // per-half load coords (128 threads cover the whole tile)
    const int kr = htid >> 1, kh = htid & 1;     // K: 2 threads/row, 4 ch each
    const int vr = htid >> 2, vq = htid & 3;     // V: 4 threads/row, 4 ch each

    // ---- prologue: issue tile 0 into stage 0 ----
    {
        const char* kg = kgb;
        const char* vg = vgb;
        uint32_t ka = hbase_a;
        uint32_t va = ka + KBUFU*4;
        #pragma unroll
        for (int j = 0; j < 4; j++)
            cpa16(ka + kr*160 + kh*64 + j*16, kg + kr*128 + kh*64 + j*16);
        #pragma unroll
        for (int j = 0; j < 4; j++)
            cpa16(va + vr*288 + vq*64 + j*16, vg + vr*256 + vq*64 + j*16);
        CP_COMMIT();
    }

    // ---- prefetch mask fragments for tile 0 ----
    uint4 am[4];
    am[0] = mfb[0]; am[1] = mfb[32]; am[2] = mfb[64]; am[3] = mfb[96];

    for (int kt = 0; kt < NKT; kt++) {
        CP_WAIT0();
        HBAR(1 + hb);

        // ---- issue tile kt+1 into the other stage (safe: that stage was
        //      consumed at kt-1, and every half-thread passed HBAR since) ----
        if (kt + 1 < NKT) {
            const char* kg = kgb + (size_t)(kt+1)*BK*128;
            const char* vg = vgb + (size_t)(kt+1)*(BK/2)*256;
            uint32_t ka = hbase_a + (uint32_t)((kt+1) & 1)*STAGEU*4u;
            uint32_t va = ka + KBUFU*4;
            #pragma unroll
            for (int j = 0; j < 4; j++)
                cpa16(ka + kr*160 + kh*64 + j*16, kg + kr*128 + kh*64 + j*16);
            #pragma unroll
            for (int j = 0; j < 4; j++)
                cpa16(va + vr*288 + vq*64 + j*16, vg + vr*256 + vq*64 + j*16);
            CP_COMMIT();
        }

        const uint32_t* Khu = smu + hbase_u + (uint32_t)(kt & 1)*STAGEU;
        const uint32_t* Vsu = Khu + KBUFU;

        // ---- per 16-k chunk: S-MMA (LDS.64) -> ex2/mask -> PV ----
        #pragma unroll
        for (int c4 = 0; c4 < 4; c4++) {
            float aE[4] = {0.f,0.f,0.f,0.f}, aO[4] = {0.f,0.f,0.f,0.f};
            const uint32_t* krE = &Khu[(16*c4 + g)*KSTRU + 2*t];
            const uint32_t* krO = &Khu[(16*c4 + 8 + g)*KSTRU + 2*t];
            #pragma unroll
            for (int d4 = 0; d4 < 4; d4++) {
                uint2 kbE = *(const uint2*)&krE[8*d4];
                uint2 kbO = *(const uint2*)&krO[8*d4];
                mma16bf(aE, Qf[d4], kbE.x, kbE.y);
                mma16bf(aO, Qf[d4], kbO.x, kbO.y);
            }
            uint32_t hEl = h2(aE[0], aE[1]), hEh = h2(aE[2], aE[3]);
            uint32_t hOl = h2(aO[0], aO[1]), hOh = h2(aO[2], aO[3]);
            lsum2_lo = hadd2u(lsum2_lo, hadd2u(ex2h2(hEl), ex2h2(hOl)));
            lsum2_hi = hadd2u(lsum2_hi, hadd2u(ex2h2(hEh), ex2h2(hOh)));
            const uint4 amc = am[c4];
            uint32_t a1f[4], a2f[4];
            a1f[0] = hEl & amc.x;  a2f[0] = amc.x & 0x3C003C00u;
            a1f[1] = hEh & amc.y;  a2f[1] = amc.y & 0x3C003C00u;
            a1f[2] = hOl & amc.z;  a2f[2] = amc.z & 0x3C003C00u;
            a1f[3] = hOh & amc.w;  a2f[3] = amc.w & 0x3C003C00u;
            const uint32_t* vrl = &Vsu[(8*c4 + t    )*VSTRU];
            const uint32_t* vrh = &Vsu[(8*c4 + t + 4)*VSTRU];
            #pragma unroll
            for (int nb = 0; nb < 8; nb++) {
                uint32_t b0 = vrl[8*nb + g];
                uint32_t b1 = vrh[8*nb + g];
                mma16f(A1[nb], a1f, b0, b1);
                mma16f(A2[nb], a2f, b0, b1);
            }
        }

        // ---- prefetch mask fragments for tile kt+1 ----
        if (kt + 1 < NKT) {
            const uint4* mfp = mfb + (size_t)(kt+1)*128;
            am[0] = mfp[0]; am[1] = mfp[32]; am[2] = mfp[64]; am[3] = mfp[96];
        }
    }

    // ---- lse: fp16x2 shfl-reduce over the 4 lanes of each group ----
    lsum2_lo = hadd2u(lsum2_lo, __shfl_xor_sync(0xffffffffu, lsum2_lo, 1));
    lsum2_lo = hadd2u(lsum2_lo, __shfl_xor_sync(0xffffffffu, lsum2_lo, 2));
    lsum2_hi = hadd2u(lsum2_hi, __shfl_xor_sync(0xffffffffu, lsum2_hi, 1));
    lsum2_hi = hadd2u(lsum2_hi, __shfl_xor_sync(0xffffffffu, lsum2_hi, 2));
    float2 flo = __half22float2(*(__half2*)&lsum2_lo);
    float2 fhi = __half22float2(*(__half2*)&lsum2_hi);
    const float lse_lo = __logf(flo.x + flo.y);
    const float lse_hi = __logf(fhi.x + fhi.y);

    // ---- epilogue: out = (ln2*A1 - lse*A2) - 1e9*(vs - A2) ----
    __syncthreads();   // single CTA-wide join (vs_s visibility)
    const int b = bh >> 4, h = bh & 15;
    float* olo = gout + ((size_t)b*SS_ + qlo)*(HH*DD) + h*DD;
    float* ohi = gout + ((size_t)b*SS_ + qhi)*(HH*DD) + h*DD;
    #pragma unroll
    for (int nb = 0; nb < 8; nb++) {
        int d = 8*nb + 2*t;
        float vs0 = vs_s[d], vs1 = vs_s[d + 1];
        float o0 = (LN2*A1[nb][0] - lse_lo*A2[nb][0]) - 1e9f*(vs0 - A2[nb][0]);
        float o1 = (LN2*A1[nb][1] - lse_lo*A2[nb][1]) - 1e9f*(vs1 - A2[nb][1]);
        float o2 = (LN2*A1[nb][2] - lse_hi*A2[nb][2]) - 1e9f*(vs0 - A2[nb][2]);
        float o3 = (LN2*A1[nb][3] - lse_hi*A2[nb][3]) - 1e9f*(vs1 - A2[nb][3]);
        *(float2*)&olo[d] = make_float2(o0, o1);
        *(float2*)&ohi[d] = make_float2(o2, o3);
    }
}

// ---------------------------------------------------------------------------
extern "C" void kernel_launch(void* const* d_in, const int* in_sizes, int n_in,
                              void* d_out, int out_size) {
    const float* q    = (const float*)d_in[0];
    const float* k    = (const float*)d_in[1];
    const float* v    = (const float*)d_in[2];
    const int*   mask = (const int*)d_in[3];
    float* out = (float*)d_out;

    const int dsm = 2*2*STAGEU*4;   // 77824 bytes (2 halves x 2 stages)
    cudaFuncSetAttribute(attn_kernel,
                         cudaFuncAttributeMaxDynamicSharedMemorySize, dsm);

    prep_kernel<<<10752, 256>>>(k, v, mask);
    attn_kernel<<<NBH*(SS_/BQ), NT, dsm>>>(q, out);
}

// round 16
// speedup vs baseline: 1.3623x; 1.3623x over previous
#include <cuda_runtime.h>
#include <cuda_fp16.h>
#include <cstdint>

#define BB 4
#define HH 16
#define SS_ 2048
#define DD 64
#define BQ 128
#define BK 64
#define NKT 32
#define NBH 64
#define NT 256
#define VSTRU 72   /* V fp16x2 smem row stride in u32 */
#define KSTRU 40   /* K bf16x2 smem row stride in u32: LDS.64 conflict-free */
#define KBUFU (64*KSTRU)       /* 2560 u32 */
#define VBUFU (32*VSTRU)       /* 2304 u32 */
#define STAGEU (KBUFU+VBUFU)   /* 4864 u32 = 19456 B */
#define NSTAGE 4
#define LOG2E 1.4426950408889634f
#define LN2   0.6931471805599453f

__device__ float    g_vpart[NBH*8*64];               /* vsum partials */
__device__ uint32_t g_kbf[(size_t)NBH*SS_*(DD/2)];   /* bf16x2, permuted d-pair cols */
__device__ uint32_t g_vh [(size_t)NBH*(SS_/2)*DD];   /* fp16x2 pairs along k (plain) */
__device__ uint4    g_mfrag[524288];

// ---------------- helpers ----------------
__device__ __forceinline__ uint32_t smem_u32(const void* p) {
    uint32_t a;
    asm("{ .reg .u64 t; cvta.to.shared.u64 t, %1; cvt.u32.u64 %0, t; }"
        : "=r"(a) : "l"(p));
    return a;
}
__device__ __forceinline__ uint32_t bf2(float lo, float hi) {
    uint32_t r; asm("cvt.rn.bf16x2.f32 %0, %1, %2;" : "=r"(r) : "f"(hi), "f"(lo));
    return r;
}
__device__ __forceinline__ uint32_t h2(float lo, float hi) {
    uint32_t r; asm("cvt.rn.f16x2.f32 %0, %1, %2;" : "=r"(r) : "f"(hi), "f"(lo));
    return r;
}
__device__ __forceinline__ uint32_t ex2h2(uint32_t a) {
    uint32_t d; asm("ex2.approx.f16x2 %0, %1;" : "=r"(d) : "r"(a)); return d;
}
__device__ __forceinline__ uint32_t hadd2u(uint32_t a, uint32_t b) {
    uint32_t d; asm("add.rn.f16x2 %0, %1, %2;" : "=r"(d) : "r"(a), "r"(b)); return d;
}
__device__ __forceinline__ void mma16bf(float* d, const uint32_t* a,
                                        uint32_t b0, uint32_t b1) {
    asm volatile(
        "mma.sync.aligned.m16n8k16.row.col.f32.bf16.bf16.f32 "
        "{%0,%1,%2,%3}, {%4,%5,%6,%7}, {%8,%9}, {%0,%1,%2,%3};"
        : "+f"(d[0]), "+f"(d[1]), "+f"(d[2]), "+f"(d[3])
        : "r"(a[0]), "r"(a[1]), "r"(a[2]), "r"(a[3]), "r"(b0), "r"(b1));
}
__device__ __forceinline__ void mma16f(float* d, const uint32_t* a,
                                       uint32_t b0, uint32_t b1) {
    asm volatile(
        "mma.sync.aligned.m16n8k16.row.col.f32.f16.f16.f32 "
        "{%0,%1,%2,%3}, {%4,%5,%6,%7}, {%8,%9}, {%0,%1,%2,%3};"
        : "+f"(d[0]), "+f"(d[1]), "+f"(d[2]), "+f"(d[3])
        : "r"(a[0]), "r"(a[1]), "r"(a[2]), "r"(a[3]), "r"(b0), "r"(b1));
}
__device__ __forceinline__ void cpa16(uint32_t sdst, const void* gsrc) {
    asm volatile("cp.async.cg.shared.global [%0], [%1], 16;"
                 :: "r"(sdst), "l"(gsrc));
}

// ---------------------------------------------------------------------------
// prep: mask-fragments + K->bf16x2(permuted) + V->fp16x2(plain) + vsum512
// ---------------------------------------------------------------------------
__global__ void prep_kernel(const float* __restrict__ gk,
                            const float* __restrict__ gv,
                            const int*   __restrict__ gm)
{
    __shared__ float red[4][64];
    const int bid = blockIdx.x, tid = threadIdx.x;

    if (bid < 2048) {                       // mask AND-fragments
        int i  = bid*256 + tid;
        int t  = i & 3;
        int g  = (i >> 2) & 7;
        int c4 = (i >> 5) & 3;
        int kt = (i >> 7) & 31;
        int pp = i >> 12;
        int qlo = pp*16 + g, qhi = qlo + 8;
        int kE  = kt*64 + 16*c4 + 2*t, kO = kE + 8;
        const int* ml = gm + (size_t)qlo*SS_;
        const int* mh = gm + (size_t)qhi*SS_;
        uint4 o;
        o.x = (ml[kE] ? 0xFFFFu : 0u) | (ml[kE+1] ? 0xFFFF0000u : 0u);
        o.y = (mh[kE] ? 0xFFFFu : 0u) | (mh[kE+1] ? 0xFFFF0000u : 0u);
        o.z = (ml[kO] ? 0xFFFFu : 0u) | (ml[kO+1] ? 0xFFFF0000u : 0u);
        o.w = (mh[kO] ? 0xFFFFu : 0u) | (mh[kO+1] ? 0xFFFF0000u : 0u);
        g_mfrag[i] = o;
    } else if (bid < 6144) {                // K -> bf16x2, permuted d-pair cols
        size_t i = (size_t)(bid - 2048)*256 + tid;
        const float4* src = (const float4*)gk + i*2;
        float4 a = src[0], b = src[1];
        size_t row = i >> 3;
        int    aa  = (int)(i & 7);
        uint32_t* dst = g_kbf + row*64 + 8*(aa >> 1) + (aa & 1);
        dst[0] = bf2(a.x, a.y);
        dst[2] = bf2(a.z, a.w);
        dst[4] = bf2(b.x, b.y);
        dst[6] = bf2(b.z, b.w);
    } else if (bid < 10240) {               // V -> fp16x2 (pairs along k, plain)
        size_t i = (size_t)(bid - 6144)*256 + tid;
        size_t R = i >> 4;
        int    q = (int)(i & 15);
        const float4* v4 = (const float4*)gv;
        float4 f0 = v4[(2*R    )*16 + q];
        float4 f1 = v4[(2*R + 1)*16 + q];
        uint4 o;
        o.x = h2(f0.x, f1.x); o.y = h2(f0.y, f1.y);
        o.z = h2(f0.z, f1.z); o.w = h2(f0.w, f1.w);
        ((uint4*)g_vh)[i] = o;
    } else {                                // vsum partials: 512 blocks
        int blk  = bid - 10240;
        int bh   = blk >> 3, part = blk & 7;
        int d = tid & 63, strip = tid >> 6;
        const float* vp = gv + (size_t)bh*SS_*DD + (size_t)part*256*DD;
        float a0 = 0.f, a1 = 0.f, a2 = 0.f, a3 = 0.f;
        #pragma unroll 4
        for (int k = strip; k < 256; k += 16) {
            a0 += vp[(k     )*DD + d];
            a1 += vp[(k +  4)*DD + d];
            a2 += vp[(k +  8)*DD + d];
            a3 += vp[(k + 12)*DD + d];
        }
        red[strip][d] = (a0 + a1) + (a2 + a3);
        __syncthreads();
        if (strip == 0)
            g_vpart[blk*64 + d] = red[0][d] + red[1][d] + red[2][d] + red[3][d];
    }
}

// ---------------------------------------------------------------------------
// main attention kernel — R12 attn verbatim (best measured)
//   out = (ln2*A1 - lse*A2) - 1e9*(A3 - A2);  S-mma emits s*log2e
// ---------------------------------------------------------------------------
__global__ void __launch_bounds__(NT, 2)
attn_kernel(const float* __restrict__ gq, float* __restrict__ gout)
{
    extern __shared__ uint32_t smu[];
    __shared__ float vs_s[64];

    const uint32_t smbase = smem_u32(smu);

    const int tid = threadIdx.x;
    const int w   = tid >> 5;
    const int lane = tid & 31;
    const int g = lane >> 2;
    const int t = lane & 3;
    const int bid = blockIdx.x;
    const int bh  = bid >> 4;
    const int qt  = bid & 15;
    const int qbase = qt * BQ;
    const int qlo = qbase + 16*w + g;
    const int qhi = qlo + 8;

    // vsum: deterministic fixed-order sum of the 8 partials
    if (tid < 64) {
        const float* vpp = g_vpart + (size_t)bh*8*64 + tid;
        float s = 0.f;
        #pragma unroll
        for (int p = 0; p < 8; p++) s += vpp[p*64];
        vs_s[tid] = s;
    }

    // ---- persistent Q fragments: bf16 pairs, pre-scaled by log2e/8 ----
    uint32_t Qf[4][4];
    {
        const float qs = 0.125f * LOG2E;
        const float* ql = gq + (size_t)bh*SS_*DD + (size_t)qlo*DD;
        const float* qh = gq + (size_t)bh*SS_*DD + (size_t)qhi*DD;
        #pragma unroll
        for (int c4 = 0; c4 < 4; c4++) {
            int k0 = 16*c4 + 2*t;
            Qf[c4][0] = bf2(qs*ql[k0    ], qs*ql[k0 + 1]);
            Qf[c4][1] = bf2(qs*qh[k0    ], qs*qh[k0 + 1]);
            Qf[c4][2] = bf2(qs*ql[k0 + 8], qs*ql[k0 + 9]);
            Qf[c4][3] = bf2(qs*qh[k0 + 8], qs*qh[k0 + 9]);
        }
    }

    const char* kgb = (const char*)g_kbf + (size_t)bh*SS_*128;
    const char* vgb = (const char*)g_vh  + (size_t)bh*(SS_/2)*256;
    const uint4* mfb = g_mfrag + (((size_t)(qt*8 + w)*32)*4)*32 + lane;

    float A1[8][4], A2[8][4];
    #pragma unroll
    for (int nb = 0; nb < 8; nb++)
        #pragma unroll
        for (int j = 0; j < 4; j++) { A1[nb][j] = 0.f; A2[nb][j] = 0.f; }
    uint32_t lsum2_lo = 0u, lsum2_hi = 0u;

    const int kr0 = tid >> 3, kc0 = tid & 7;
    const int vr0 = tid >> 4, vc0 = tid & 15;

    // ---- prologue: issue tiles 0..NSTAGE-2 ----
    #pragma unroll
    for (int pt = 0; pt < NSTAGE-1; pt++) {
        uint32_t ka = smbase + pt*(STAGEU*4);
        uint32_t va = ka + KBUFU*4;
        const char* kg = kgb + (size_t)pt*BK*128;
        const char* vg = vgb + (size_t)pt*(BK/2)*256;
        cpa16(ka + kr0*160 + kc0*16,        kg + kr0*128 + kc0*16);
        cpa16(ka + (kr0+32)*160 + kc0*16,   kg + (kr0+32)*128 + kc0*16);
        cpa16(va + vr0*288 + vc0*16,        vg + vr0*256 + vc0*16);
        cpa16(va + (vr0+16)*288 + vc0*16,   vg + (vr0+16)*256 + vc0*16);
        asm volatile("cp.async.commit_group;" ::: "memory");
    }

    // ---- prefetch mask fragments for tile 0 ----
    uint4 am[4];
    am[0] = mfb[0]; am[1] = mfb[32]; am[2] = mfb[64]; am[3] = mfb[96];

    for (int kt = 0; kt < NKT; kt++) {
        asm volatile("cp.async.wait_group %0;" :: "n"(NSTAGE-2) : "memory");
        __syncthreads();

        // ---- issue tile kt+NSTAGE-1 ----
        if (kt + NSTAGE-1 < NKT) {
            int st = (kt + NSTAGE-1) % NSTAGE;
            uint32_t ka = smbase + st*(STAGEU*4);
            uint32_t va = ka + KBUFU*4;
            const char* kg = kgb + (size_t)(kt+NSTAGE-1)*BK*128;
            const char* vg = vgb + (size_t)(kt+NSTAGE-1)*(BK/2)*256;
            cpa16(ka + kr0*160 + kc0*16,       kg + kr0*128 + kc0*16);
            cpa16(ka + (kr0+32)*160 + kc0*16,  kg + (kr0+32)*128 + kc0*16);
            cpa16(va + vr0*288 + vc0*16,       vg + vr0*256 + vc0*16);
            cpa16(va + (vr0+16)*288 + vc0*16,  vg + (vr0+16)*256 + vc0*16);
            asm volatile("cp.async.commit_group;" ::: "memory");
        }

        const uint32_t* Khu = smu + (kt % NSTAGE)*STAGEU;
        const uint32_t* Vsu = Khu + KBUFU;

        // ---- per 16-k chunk: S-MMA (LDS.64) -> ex2/mask -> PV ----
        #pragma unroll
        for (int c4 = 0; c4 < 4; c4++) {
            float aE[4] = {0.f,0.f,0.f,0.f}, aO[4] = {0.f,0.f,0.f,0.f};
            const uint32_t* krE = &Khu[(16*c4 + g)*KSTRU + 2*t];
            const uint32_t* krO = &Khu[(16*c4 + 8 + g)*KSTRU + 2*t];
            #pragma unroll
            for (int d4 = 0; d4 < 4; d4++) {
                uint2 kbE = *(const uint2*)&krE[8*d4];
                uint2 kbO = *(const uint2*)&krO[8*d4];
                mma16bf(aE, Qf[d4], kbE.x, kbE.y);
                mma16bf(aO, Qf[d4], kbO.x, kbO.y);
            }
            uint32_t hEl = h2(aE[0], aE[1]), hEh = h2(aE[2], aE[3]);
            uint32_t hOl = h2(aO[0], aO[1]), hOh = h2(aO[2], aO[3]);
            lsum2_lo = hadd2u(lsum2_lo, hadd2u(ex2h2(hEl), ex2h2(hOl)));
            lsum2_hi = hadd2u(lsum2_hi, hadd2u(ex2h2(hEh), ex2h2(hOh)));
            const uint4 amc = am[c4];
            uint32_t a1f[4], a2f[4];
            a1f[0] = hEl & amc.x;  a2f[0] = amc.x & 0x3C003C00u;
            a1f[1] = hEh & amc.y;  a2f[1] = amc.y & 0x3C003C00u;
            a1f[2] = hOl & amc.z;  a2f[2] = amc.z & 0x3C003C00u;
            a1f[3] = hOh & amc.w;  a2f[3] = amc.w & 0x3C003C00u;
            const uint32_t* vrl = &Vsu[(8*c4 + t    )*VSTRU];
            const uint32_t* vrh = &Vsu[(8*c4 + t + 4)*VSTRU];
            #pragma unroll
            for (int nb = 0; nb < 8; nb++) {
                uint32_t b0 = vrl[8*nb + g];
                uint32_t b1 = vrh[8*nb + g];
                mma16f(A1[nb], a1f, b0, b1);
                mma16f(A2[nb], a2f, b0, b1);
            }
        }

        // ---- prefetch mask fragments for tile kt+1 ----
        if (kt + 1 < NKT) {
            const uint4* mfp = mfb + (size_t)(kt+1)*128;
            am[0] = mfp[0]; am[1] = mfp[32]; am[2] = mfp[64]; am[3] = mfp[96];
        }
    }

    // ---- lse: fp16x2 shfl-reduce over the 4 lanes of each group ----
    lsum2_lo = hadd2u(lsum2_lo, __shfl_xor_sync(0xffffffffu, lsum2_lo, 1));
    lsum2_lo = hadd2u(lsum2_lo, __shfl_xor_sync(0xffffffffu, lsum2_lo, 2));
    lsum2_hi = hadd2u(lsum2_hi, __shfl_xor_sync(0xffffffffu, lsum2_hi, 1));
    lsum2_hi = hadd2u(lsum2_hi, __shfl_xor_sync(0xffffffffu, lsum2_hi, 2));
    float2 flo = __half22float2(*(__half2*)&lsum2_lo);
    float2 fhi = __half22float2(*(__half2*)&lsum2_hi);
    const float lse_lo = __logf(flo.x + flo.y);
    const float lse_hi = __logf(fhi.x + fhi.y);

    // ---- epilogue: out = (ln2*A1 - lse*A2) - 1e9*(vs - A2) ----
    __syncthreads();
    const int b = bh >> 4, h = bh & 15;
    float* olo = gout + ((size_t)b*SS_ + qlo)*(HH*DD) + h*DD;
    float* ohi = gout + ((size_t)b*SS_ + qhi)*(HH*DD) + h*DD;
    #pragma unroll
    for (int nb = 0; nb < 8; nb++) {
        int d = 8*nb + 2*t;
        float vs0 = vs_s[d], vs1 = vs_s[d + 1];
        float o0 = (LN2*A1[nb][0] - lse_lo*A2[nb][0]) - 1e9f*(vs0 - A2[nb][0]);
        float o1 = (LN2*A1[nb][1] - lse_lo*A2[nb][1]) - 1e9f*(vs1 - A2[nb][1]);
        float o2 = (LN2*A1[nb][2] - lse_hi*A2[nb][2]) - 1e9f*(vs0 - A2[nb][2]);
        float o3 = (LN2*A1[nb][3] - lse_hi*A2[nb][3]) - 1e9f*(vs1 - A2[nb][3]);
        *(float2*)&olo[d] = make_float2(o0, o1);
        *(float2*)&ohi[d] = make_float2(o2, o3);
    }
}

// ---------------------------------------------------------------------------
extern "C" void kernel_launch(void* const* d_in, const int* in_sizes, int n_in,
                              void* d_out, int out_size) {
    const float* q    = (const float*)d_in[0];
    const float* k    = (const float*)d_in[1];
    const float* v    = (const float*)d_in[2];
    const int*   mask = (const int*)d_in[3];
    float* out = (float*)d_out;

    const int dsm = NSTAGE*STAGEU*4;   // 77824 bytes
    cudaFuncSetAttribute(attn_kernel,
                         cudaFuncAttributeMaxDynamicSharedMemorySize, dsm);

    prep_kernel<<<10752, 256>>>(k, v, mask);
    attn_kernel<<<NBH*(SS_/BQ), NT, dsm>>>(q, out);
}

// round 17
// speedup vs baseline: 1.3904x; 1.0206x over previous
#include <cuda_runtime.h>
#include <cuda_fp16.h>
#include <cstdint>

#define BB 4
#define HH 16
#define SS_ 2048
#define DD 64
#define BQ 128
#define BK2 128                /* big k-tile */
#define NKT2 16
#define NBH 64
#define NT 256
#define VSTRU 72               /* V fp16x2 smem row stride in u32 */
#define KSTRU 40               /* K bf16x2 smem row stride in u32 (LDS.64) */
#define KBUFU (128*KSTRU)      /* 5120 u32 */
#define VBUFU (64*VSTRU)       /* 4608 u32 */
#define STAGEU (KBUFU+VBUFU)   /* 9728 u32 = 38912 B */
#define LOG2E 1.4426950408889634f
#define LN2   0.6931471805599453f

__device__ float    g_vpart[NBH*8*64];               /* vsum partials */
__device__ uint32_t g_kbf[(size_t)NBH*SS_*(DD/2)];   /* bf16x2, permuted d-pair cols */
__device__ uint32_t g_vh [(size_t)NBH*(SS_/2)*DD];   /* fp16x2 pairs along k (plain) */
__device__ uint4    g_mfrag[524288];

// ---------------- helpers ----------------
__device__ __forceinline__ uint32_t smem_u32(const void* p) {
    uint32_t a;
    asm("{ .reg .u64 t; cvta.to.shared.u64 t, %1; cvt.u32.u64 %0, t; }"
        : "=r"(a) : "l"(p));
    return a;
}
__device__ __forceinline__ uint32_t bf2(float lo, float hi) {
    uint32_t r; asm("cvt.rn.bf16x2.f32 %0, %1, %2;" : "=r"(r) : "f"(hi), "f"(lo));
    return r;
}
__device__ __forceinline__ uint32_t h2(float lo, float hi) {
    uint32_t r; asm("cvt.rn.f16x2.f32 %0, %1, %2;" : "=r"(r) : "f"(hi), "f"(lo));
    return r;
}
__device__ __forceinline__ uint32_t ex2h2(uint32_t a) {
    uint32_t d; asm("ex2.approx.f16x2 %0, %1;" : "=r"(d) : "r"(a)); return d;
}
__device__ __forceinline__ uint32_t hadd2u(uint32_t a, uint32_t b) {
    uint32_t d; asm("add.rn.f16x2 %0, %1, %2;" : "=r"(d) : "r"(a), "r"(b)); return d;
}
__device__ __forceinline__ void mma16bf(float* d, const uint32_t* a,
                                        uint32_t b0, uint32_t b1) {
    asm volatile(
        "mma.sync.aligned.m16n8k16.row.col.f32.bf16.bf16.f32 "
        "{%0,%1,%2,%3}, {%4,%5,%6,%7}, {%8,%9}, {%0,%1,%2,%3};"
        : "+f"(d[0]), "+f"(d[1]), "+f"(d[2]), "+f"(d[3])
        : "r"(a[0]), "r"(a[1]), "r"(a[2]), "r"(a[3]), "r"(b0), "r"(b1));
}
__device__ __forceinline__ void mma16f(float* d, const uint32_t* a,
                                       uint32_t b0, uint32_t b1) {
    asm volatile(
        "mma.sync.aligned.m16n8k16.row.col.f32.f16.f16.f32 "
        "{%0,%1,%2,%3}, {%4,%5,%6,%7}, {%8,%9}, {%0,%1,%2,%3};"
        : "+f"(d[0]), "+f"(d[1]), "+f"(d[2]), "+f"(d[3])
        : "r"(a[0]), "r"(a[1]), "r"(a[2]), "r"(a[3]), "r"(b0), "r"(b1));
}
__device__ __forceinline__ void cpa16(uint32_t sdst, const void* gsrc) {
    asm volatile("cp.async.cg.shared.global [%0], [%1], 16;"
                 :: "r"(sdst), "l"(gsrc));
}

// ---------------------------------------------------------------------------
// prep: mask-fragments + K->bf16x2(permuted) + V->fp16x2(plain) + vsum512
// (unchanged from R16)
// ---------------------------------------------------------------------------
__global__ void prep_kernel(const float* __restrict__ gk,
                            const float* __restrict__ gv,
                            const int*   __restrict__ gm)
{
    __shared__ float red[4][64];
    const int bid = blockIdx.x, tid = threadIdx.x;

    if (bid < 2048) {                       // mask AND-fragments
        int i  = bid*256 + tid;
        int t  = i & 3;
        int g  = (i >> 2) & 7;
        int c4 = (i >> 5) & 3;
        int kt = (i >> 7) & 31;
        int pp = i >> 12;
        int qlo = pp*16 + g, qhi = qlo + 8;
        int kE  = kt*64 + 16*c4 + 2*t, kO = kE + 8;
        const int* ml = gm + (size_t)qlo*SS_;
        const int* mh = gm + (size_t)qhi*SS_;
        uint4 o;
        o.x = (ml[kE] ? 0xFFFFu : 0u) | (ml[kE+1] ? 0xFFFF0000u : 0u);
        o.y = (mh[kE] ? 0xFFFFu : 0u) | (mh[kE+1] ? 0xFFFF0000u : 0u);
        o.z = (ml[kO] ? 0xFFFFu : 0u) | (ml[kO+1] ? 0xFFFF0000u : 0u);
        o.w = (mh[kO] ? 0xFFFFu : 0u) | (mh[kO+1] ? 0xFFFF0000u : 0u);
        g_mfrag[i] = o;
    } else if (bid < 6144) {                // K -> bf16x2, permuted d-pair cols
        size_t i = (size_t)(bid - 2048)*256 + tid;
        const float4* src = (const float4*)gk + i*2;
        float4 a = src[0], b = src[1];
        size_t row = i >> 3;
        int    aa  = (int)(i & 7);
        uint32_t* dst = g_kbf + row*64 + 8*(aa >> 1) + (aa & 1);
        dst[0] = bf2(a.x, a.y);
        dst[2] = bf2(a.z, a.w);
        dst[4] = bf2(b.x, b.y);
        dst[6] = bf2(b.z, b.w);
    } else if (bid < 10240) {               // V -> fp16x2 (pairs along k, plain)
        size_t i = (size_t)(bid - 6144)*256 + tid;
        size_t R = i >> 4;
        int    q = (int)(i & 15);
        const float4* v4 = (const float4*)gv;
        float4 f0 = v4[(2*R    )*16 + q];
        float4 f1 = v4[(2*R + 1)*16 + q];
        uint4 o;
        o.x = h2(f0.x, f1.x); o.y = h2(f0.y, f1.y);
        o.z = h2(f0.z, f1.z); o.w = h2(f0.w, f1.w);
        ((uint4*)g_vh)[i] = o;
    } else {                                // vsum partials: 512 blocks
        int blk  = bid - 10240;
        int bh   = blk >> 3, part = blk & 7;
        int d = tid & 63, strip = tid >> 6;
        const float* vp = gv + (size_t)bh*SS_*DD + (size_t)part*256*DD;
        float a0 = 0.f, a1 = 0.f, a2 = 0.f, a3 = 0.f;
        #pragma unroll 4
        for (int k = strip; k < 256; k += 16) {
            a0 += vp[(k     )*DD + d];
            a1 += vp[(k +  4)*DD + d];
            a2 += vp[(k +  8)*DD + d];
            a3 += vp[(k + 12)*DD + d];
        }
        red[strip][d] = (a0 + a1) + (a2 + a3);
        __syncthreads();
        if (strip == 0)
            g_vpart[blk*64 + d] = red[0][d] + red[1][d] + red[2][d] + red[3][d];
    }
}

// ---------------------------------------------------------------------------
// main attention kernel — BK=128 tiles, 2-stage pipeline, half the syncs
//   out = (ln2*A1 - lse*A2) - 1e9*(A3 - A2);  S-mma emits s*log2e
// ---------------------------------------------------------------------------
__global__ void __launch_bounds__(NT, 2)
attn_kernel(const float* __restrict__ gq, float* __restrict__ gout)
{
    extern __shared__ uint32_t smu[];
    __shared__ float vs_s[64];

    const uint32_t smbase = smem_u32(smu);

    const int tid = threadIdx.x;
    const int w   = tid >> 5;
    const int lane = tid & 31;
    const int g = lane >> 2;
    const int t = lane & 3;
    const int bid = blockIdx.x;
    const int bh  = bid >> 4;
    const int qt  = bid & 15;
    const int qbase = qt * BQ;
    const int qlo = qbase + 16*w + g;
    const int qhi = qlo + 8;

    if (tid < 64) {
        const float* vpp = g_vpart + (size_t)bh*8*64 + tid;
        float s = 0.f;
        #pragma unroll
        for (int p = 0; p < 8; p++) s += vpp[p*64];
        vs_s[tid] = s;
    }

    // ---- persistent Q fragments: bf16 pairs, pre-scaled by log2e/8 ----
    uint32_t Qf[4][4];
    {
        const float qs = 0.125f * LOG2E;
        const float* ql = gq + (size_t)bh*SS_*DD + (size_t)qlo*DD;
        const float* qh = gq + (size_t)bh*SS_*DD + (size_t)qhi*DD;
        #pragma unroll
        for (int c4 = 0; c4 < 4; c4++) {
            int k0 = 16*c4 + 2*t;
            Qf[c4][0] = bf2(qs*ql[k0    ], qs*ql[k0 + 1]);
            Qf[c4][1] = bf2(qs*qh[k0    ], qs*qh[k0 + 1]);
            Qf[c4][2] = bf2(qs*ql[k0 + 8], qs*ql[k0 + 9]);
            Qf[c4][3] = bf2(qs*qh[k0 + 8], qs*qh[k0 + 9]);
        }
    }

    const char* kgb = (const char*)g_kbf + (size_t)bh*SS_*128;
    const char* vgb = (const char*)g_vh  + (size_t)bh*(SS_/2)*256;
    const uint4* mfb = g_mfrag + (((size_t)(qt*8 + w)*32)*4)*32 + lane;

    float A1[8][4], A2[8][4];
    #pragma unroll
    for (int nb = 0; nb < 8; nb++)
        #pragma unroll
        for (int j = 0; j < 4; j++) { A1[nb][j] = 0.f; A2[nb][j] = 0.f; }
    uint32_t lsum2_lo = 0u, lsum2_hi = 0u;

    // per-thread load coords: K 4 chunks (rows kr0+32i), V 4 chunks
    const int kr0 = tid >> 3, kc0 = tid & 7;
    const int vr0 = tid >> 4, vc0 = tid & 15;

    // ---- prologue: issue big-tile 0 into stage 0 ----
    {
        uint32_t ka = smbase;
        uint32_t va = ka + KBUFU*4;
        #pragma unroll
        for (int i = 0; i < 4; i++)
            cpa16(ka + (kr0+32*i)*160 + kc0*16, kgb + (kr0+32*i)*128 + kc0*16);
        #pragma unroll
        for (int i = 0; i < 4; i++)
            cpa16(va + (vr0+16*i)*288 + vc0*16, vgb + (vr0+16*i)*256 + vc0*16);
        asm volatile("cp.async.commit_group;" ::: "memory");
    }

    // ---- prefetch mask fragments for first half-tile ----
    uint4 am[4];
    am[0] = mfb[0]; am[1] = mfb[32]; am[2] = mfb[64]; am[3] = mfb[96];

    for (int kt = 0; kt < NKT2; kt++) {
        asm volatile("cp.async.wait_group 0;" ::: "memory");
        __syncthreads();

        // ---- issue big-tile kt+1 into the other stage ----
        if (kt + 1 < NKT2) {
            uint32_t ka = smbase + (uint32_t)((kt+1) & 1)*STAGEU*4u;
            uint32_t va = ka + KBUFU*4;
            const char* kg = kgb + (size_t)(kt+1)*BK2*128;
            const char* vg = vgb + (size_t)(kt+1)*(BK2/2)*256;
            #pragma unroll
            for (int i = 0; i < 4; i++)
                cpa16(ka + (kr0+32*i)*160 + kc0*16, kg + (kr0+32*i)*128 + kc0*16);
            #pragma unroll
            for (int i = 0; i < 4; i++)
                cpa16(va + (vr0+16*i)*288 + vc0*16, vg + (vr0+16*i)*256 + vc0*16);
            asm volatile("cp.async.commit_group;" ::: "memory");
        }

        const uint32_t* Khu0 = smu + (uint32_t)(kt & 1)*STAGEU;
        const uint32_t* Vsu0 = Khu0 + KBUFU;

        // ---- two 64-k halves, each 4 chunks; am reloaded between halves ----
        #pragma unroll
        for (int hf = 0; hf < 2; hf++) {
            const uint32_t* Khu = Khu0 + hf*64*KSTRU;
            const uint32_t* Vsu = Vsu0 + hf*32*VSTRU;

            #pragma unroll
            for (int c4 = 0; c4 < 4; c4++) {
                float aE[4] = {0.f,0.f,0.f,0.f}, aO[4] = {0.f,0.f,0.f,0.f};
                const uint32_t* krE = &Khu[(16*c4 + g)*KSTRU + 2*t];
                const uint32_t* krO = &Khu[(16*c4 + 8 + g)*KSTRU + 2*t];
                #pragma unroll
                for (int d4 = 0; d4 < 4; d4++) {
                    uint2 kbE = *(const uint2*)&krE[8*d4];
                    uint2 kbO = *(const uint2*)&krO[8*d4];
                    mma16bf(aE, Qf[d4], kbE.x, kbE.y);
                    mma16bf(aO, Qf[d4], kbO.x, kbO.y);
                }
                uint32_t hEl = h2(aE[0], aE[1]), hEh = h2(aE[2], aE[3]);
                uint32_t hOl = h2(aO[0], aO[1]), hOh = h2(aO[2], aO[3]);
                lsum2_lo = hadd2u(lsum2_lo, hadd2u(ex2h2(hEl), ex2h2(hOl)));
                lsum2_hi = hadd2u(lsum2_hi, hadd2u(ex2h2(hEh), ex2h2(hOh)));
                const uint4 amc = am[c4];
                uint32_t a1f[4], a2f[4];
                a1f[0] = hEl & amc.x;  a2f[0] = amc.x & 0x3C003C00u;
                a1f[1] = hEh & amc.y;  a2f[1] = amc.y & 0x3C003C00u;
                a1f[2] = hOl & amc.z;  a2f[2] = amc.z & 0x3C003C00u;
                a1f[3] = hOh & amc.w;  a2f[3] = amc.w & 0x3C003C00u;
                const uint32_t* vrl = &Vsu[(8*c4 + t    )*VSTRU];
                const uint32_t* vrh = &Vsu[(8*c4 + t + 4)*VSTRU];
                #pragma unroll
                for (int nb = 0; nb < 8; nb++) {
                    uint32_t b0 = vrl[8*nb + g];
                    uint32_t b1 = vrh[8*nb + g];
                    mma16f(A1[nb], a1f, b0, b1);
                    mma16f(A2[nb], a2f, b0, b1);
                }
            }

            // ---- reload mask fragments for the next 64-k half ----
            int nhalf = 2*kt + hf + 1;       // global 64-k half index
            if (nhalf < 32) {
                const uint4* mfp = mfb + (size_t)nhalf*128;
                am[0] = mfp[0]; am[1] = mfp[32];
                am[2] = mfp[64]; am[3] = mfp[96];
            }
        }
    }

    // ---- lse: fp16x2 shfl-reduce over the 4 lanes of each group ----
    lsum2_lo = hadd2u(lsum2_lo, __shfl_xor_sync(0xffffffffu, lsum2_lo, 1));
    lsum2_lo = hadd2u(lsum2_lo, __shfl_xor_sync(0xffffffffu, lsum2_lo, 2));
    lsum2_hi = hadd2u(lsum2_hi, __shfl_xor_sync(0xffffffffu, lsum2_hi, 1));
    lsum2_hi = hadd2u(lsum2_hi, __shfl_xor_sync(0xffffffffu, lsum2_hi, 2));
    float2 flo = __half22float2(*(__half2*)&lsum2_lo);
    float2 fhi = __half22float2(*(__half2*)&lsum2_hi);
    const float lse_lo = __logf(flo.x + flo.y);
    const float lse_hi = __logf(fhi.x + fhi.y);

    // ---- epilogue: out = (ln2*A1 - lse*A2) - 1e9*(vs - A2) ----
    __syncthreads();
    const int b = bh >> 4, h = bh & 15;
    float* olo = gout + ((size_t)b*SS_ + qlo)*(HH*DD) + h*DD;
    float* ohi = gout + ((size_t)b*SS_ + qhi)*(HH*DD) + h*DD;
    #pragma unroll
    for (int nb = 0; nb < 8; nb++) {
        int d = 8*nb + 2*t;
        float vs0 = vs_s[d], vs1 = vs_s[d + 1];
        float o0 = (LN2*A1[nb][0] - lse_lo*A2[nb][0]) - 1e9f*(vs0 - A2[nb][0]);
        float o1 = (LN2*A1[nb][1] - lse_lo*A2[nb][1]) - 1e9f*(vs1 - A2[nb][1]);
        float o2 = (LN2*A1[nb][2] - lse_hi*A2[nb][2]) - 1e9f*(vs0 - A2[nb][2]);
        float o3 = (LN2*A1[nb][3] - lse_hi*A2[nb][3]) - 1e9f*(vs1 - A2[nb][3]);
        *(float2*)&olo[d] = make_float2(o0, o1);
        *(float2*)&ohi[d] = make_float2(o2, o3);
    }
}

// ---------------------------------------------------------------------------
extern "C" void kernel_launch(void* const* d_in, const int* in_sizes, int n_in,
                              void* d_out, int out_size) {
    const float* q    = (const float*)d_in[0];
    const float* k    = (const float*)d_in[1];
    const float* v    = (const float*)d_in[2];
    const int*   mask = (const int*)d_in[3];
    float* out = (float*)d_out;

    const int dsm = 2*STAGEU*4;   // 77824 bytes
    cudaFuncSetAttribute(attn_kernel,
                         cudaFuncAttributeMaxDynamicSharedMemorySize, dsm);

    prep_kernel<<<10752, 256>>>(k, v, mask);
    attn_kernel<<<NBH*(SS_/BQ), NT, dsm>>>(q, out);
}